// round 2
// baseline (speedup 1.0000x reference)
#include <cuda_runtime.h>
#include <math.h>

// Problem constants
#define NBC   768        // total centers = B*L*R_NEG
#define BPI   96         // centers per image = L*R_NEG
#define LANES 6
#define PP    72         // points per lane (input)
#define SS    180        // resampled points per lane
#define GT    1080       // LANES*SS gt points per image
#define FH    90
#define FW    160
#define FC    256
#define FHW   (FH*FW)    // 14400

#define TPB   128

// Scratch (allocation-free rule: __device__ globals)
__device__ float g_ce[NBC];
__device__ float g_sel[NBC];
__device__ int   g_counter = 0;

__global__ __launch_bounds__(TPB)
void loss_point_kernel(const float* __restrict__ lane_xs,
                       const float* __restrict__ lane_ys,
                       const float* __restrict__ centers,
                       const float* __restrict__ feat,
                       const float* __restrict__ Wn,
                       const float* __restrict__ bn,
                       float* __restrict__ out) {
    const int i   = blockIdx.x;    // center index
    const int t   = threadIdx.x;
    const int img = i / BPI;

    const float cx = __ldg(&centers[2 * i])     * 1280.0f;
    const float cy = __ldg(&centers[2 * i + 1]) * 720.0f;

    // validity (mirrors reference exactly)
    const float x1 = cx - 16.0f, y1 = cy - 16.0f;
    const float x2 = cx + 16.0f, y2 = cy + 16.0f;
    const bool valid =
        (x1 > 0.0f) && (x1 < 1280.0f) && (y1 >= 0.0f) && (y1 < 720.0f) &&
        (x2 >= 0.0f) && (x2 < 1280.0f) && (y2 >= 0.0f) && (y2 < 720.0f);

    // ---- min squared distance over this image's 1080 resampled gt points ----
    float md2 = 3.4e38f;
    const float scale    = (float)(PP - 1) / (float)(SS - 1);   // 71/179
    const float inv_ss   = 1.0f / (float)SS;
    for (int j = t; j < GT; j += TPB) {
        // lane l = j / SS via float reciprocal (exact for j < 1080)
        const int l = (int)((float)j * inv_ss);
        const int s = j - l * SS;
        const float src = (float)s * scale;
        int   i0 = (int)src;                 // src >= 0 -> floor
        if (i0 > PP - 1) i0 = PP - 1;
        const int   i1 = min(i0 + 1, PP - 1);
        const float w  = src - (float)i0;
        const int base = (img * LANES + l) * PP;
        const float ax = __ldg(&lane_xs[base + i0]);
        const float bx = __ldg(&lane_xs[base + i1]);
        const float ay = __ldg(&lane_ys[base + i0]);
        const float by = __ldg(&lane_ys[base + i1]);
        const float gx = (ax + (bx - ax) * w) * 1280.0f;
        const float gy = (ay + (by - ay) * w) * 720.0f;
        const float dx = cx - gx, dy = cy - gy;
        md2 = fminf(md2, dx * dx + dy * dy);
    }

    // ---- feature gather + two dot products (logits) ----
    int fx = (int)(cx * 0.125f); fx = min(max(fx, 0), FW - 1);
    int fy = (int)(cy * 0.125f); fy = min(max(fy, 0), FH - 1);
    const float* fptr = feat + (size_t)img * FC * FHW + (size_t)fy * FW + fx;

    float a0 = 0.0f, a1 = 0.0f;
    #pragma unroll
    for (int c = t; c < FC; c += TPB) {
        const float f = __ldg(fptr + (size_t)c * FHW);
        a0 += f * __ldg(&Wn[2 * c]);
        a1 += f * __ldg(&Wn[2 * c + 1]);
    }

    // ---- block reduce: min(md2), sum(a0), sum(a1) ----
    #pragma unroll
    for (int off = 16; off > 0; off >>= 1) {
        md2 = fminf(md2, __shfl_down_sync(0xFFFFFFFFu, md2, off));
        a0 += __shfl_down_sync(0xFFFFFFFFu, a0, off);
        a1 += __shfl_down_sync(0xFFFFFFFFu, a1, off);
    }
    __shared__ float smd[TPB / 32], s0[TPB / 32], s1[TPB / 32];
    __shared__ bool  s_last;
    const int wrp = t >> 5, ln = t & 31;
    if (ln == 0) { smd[wrp] = md2; s0[wrp] = a0; s1[wrp] = a1; }
    __syncthreads();

    if (t == 0) {
        md2 = fminf(fminf(smd[0], smd[1]), fminf(smd[2], smd[3]));
        a0  = s0[0] + s0[1] + s0[2] + s0[3];
        a1  = s1[0] + s1[1] + s1[2] + s1[3];

        const float md = sqrtf(md2);
        const float thr_lo = 22.62741699796952f;        // sqrt(2)*16
        const bool sel = valid && (md > thr_lo) && (md < 130.0f);

        const float l0 = a0 + bn[0];
        const float l1 = a1 + bn[1];
        const float d  = l1 - l0;
        // ce = logsumexp([l0,l1]) - l0, numerically stable
        const float ce = fmaxf(d, 0.0f) + log1pf(expf(-fabsf(d)));

        g_ce[i]  = sel ? ce : 0.0f;
        g_sel[i] = sel ? 1.0f : 0.0f;
        __threadfence();
        const int ticket = atomicAdd(&g_counter, 1);
        s_last = (ticket == NBC - 1);
    }
    __syncthreads();

    // ---- last block performs the deterministic final reduction ----
    if (s_last) {
        __threadfence();
        float ce = 0.0f, sl = 0.0f;
        for (int k = t; k < NBC; k += TPB) { ce += g_ce[k]; sl += g_sel[k]; }
        #pragma unroll
        for (int off = 16; off > 0; off >>= 1) {
            ce += __shfl_down_sync(0xFFFFFFFFu, ce, off);
            sl += __shfl_down_sync(0xFFFFFFFFu, sl, off);
        }
        if (ln == 0) { s0[wrp] = ce; s1[wrp] = sl; }
        __syncthreads();
        if (t == 0) {
            ce = s0[0] + s0[1] + s0[2] + s0[3];
            sl = s1[0] + s1[1] + s1[2] + s1[3];
            out[0] = ce / fmaxf(sl, 1.0f);
            g_counter = 0;   // reset for next graph replay
        }
    }
}

extern "C" void kernel_launch(void* const* d_in, const int* in_sizes, int n_in,
                              void* d_out, int out_size) {
    const float* lane_xs = (const float*)d_in[0];
    const float* lane_ys = (const float*)d_in[1];
    const float* centers = (const float*)d_in[2];
    const float* feat    = (const float*)d_in[3];
    const float* Wn      = (const float*)d_in[4];
    const float* bn      = (const float*)d_in[5];
    float* out = (float*)d_out;

    loss_point_kernel<<<NBC, TPB>>>(lane_xs, lane_ys, centers, feat, Wn, bn, out);
}

// round 4
// speedup vs baseline: 1.0663x; 1.0663x over previous
#include <cuda_runtime.h>
#include <math.h>

// Problem constants
#define NBC   768        // total centers = B*L*R_NEG
#define BPI   96         // centers per image = L*R_NEG
#define LANES 6
#define PP    72         // points per lane (input)
#define SS    180        // resampled points per lane
#define FH    90
#define FW    160
#define FC    256
#define FHW   (FH*FW)    // 14400
#define LPI   (LANES*PP) // 432 floats of lane data per image per axis

#define TPB   128

// Scratch (allocation-free rule: __device__ globals)
__device__ float g_ce[NBC];
__device__ float g_sel[NBC];
__device__ int   g_counter = 0;

__global__ __launch_bounds__(TPB)
void loss_point_kernel(const float* __restrict__ lane_xs,
                       const float* __restrict__ lane_ys,
                       const float* __restrict__ centers,
                       const float* __restrict__ feat,
                       const float* __restrict__ Wn,
                       const float* __restrict__ bn,
                       float* __restrict__ out) {
    const int i   = blockIdx.x;    // center index
    const int t   = threadIdx.x;
    const int img = i / BPI;

    __shared__ float s_x[LPI];     // this image's lane_xs rows
    __shared__ float s_y[LPI];     // this image's lane_ys rows
    __shared__ float smd[TPB / 32], s0[TPB / 32], s1[TPB / 32];
    __shared__ bool  s_last;

    const float cx = __ldg(&centers[2 * i])     * 1280.0f;
    const float cy = __ldg(&centers[2 * i + 1]) * 720.0f;

    // ---- prefetch (independent, DRAM-latency): feature channels + W ----
    int fx = (int)(cx * 0.125f); fx = min(max(fx, 0), FW - 1);
    int fy = (int)(cy * 0.125f); fy = min(max(fy, 0), FH - 1);
    const float* fptr = feat + (size_t)img * FC * FHW + (size_t)fy * FW + fx;
    const float f0 = __ldg(fptr + (size_t)t * FHW);
    const float f1 = __ldg(fptr + (size_t)(t + TPB) * FHW);
    const float2 w0 = __ldg((const float2*)Wn + t);
    const float2 w1 = __ldg((const float2*)Wn + t + TPB);

    // ---- stage lane data in smem (coalesced) ----
    const float* lx = lane_xs + img * LPI;
    const float* ly = lane_ys + img * LPI;
    #pragma unroll
    for (int k = t; k < LPI; k += TPB) {
        s_x[k] = __ldg(lx + k);
        s_y[k] = __ldg(ly + k);
    }
    __syncthreads();

    // validity (mirrors reference exactly)
    const float x1 = cx - 16.0f, y1 = cy - 16.0f;
    const float x2 = cx + 16.0f, y2 = cy + 16.0f;
    const bool valid =
        (x1 > 0.0f) && (x1 < 1280.0f) && (y1 >= 0.0f) && (y1 < 720.0f) &&
        (x2 >= 0.0f) && (x2 < 1280.0f) && (y2 >= 0.0f) && (y2 < 720.0f);

    // ---- min squared distance, s-major: weights once per s, reuse for 6 lanes ----
    float md2 = 3.4e38f;
    const float scale = (float)(PP - 1) / (float)(SS - 1);   // 71/179
    for (int s = t; s < SS; s += TPB) {
        const float src = (float)s * scale;
        int i0 = (int)src;                    // src >= 0 -> floor
        if (i0 > PP - 1) i0 = PP - 1;
        const int   i1 = min(i0 + 1, PP - 1);
        const float w  = src - (float)i0;
        #pragma unroll
        for (int l = 0; l < LANES; l++) {
            const int base = l * PP;
            const float ax = s_x[base + i0];
            const float bx = s_x[base + i1];
            const float ay = s_y[base + i0];
            const float by = s_y[base + i1];
            const float gx = (ax + (bx - ax) * w) * 1280.0f;
            const float gy = (ay + (by - ay) * w) * 720.0f;
            const float dx = cx - gx, dy = cy - gy;
            md2 = fminf(md2, fmaf(dx, dx, dy * dy));
        }
    }

    // ---- consume prefetched features: two dot products ----
    float a0 = fmaf(f0, w0.x, f1 * w1.x);
    float a1 = fmaf(f0, w0.y, f1 * w1.y);

    // ---- block reduce: min(md2), sum(a0), sum(a1) ----
    #pragma unroll
    for (int off = 16; off > 0; off >>= 1) {
        md2 = fminf(md2, __shfl_down_sync(0xFFFFFFFFu, md2, off));
        a0 += __shfl_down_sync(0xFFFFFFFFu, a0, off);
        a1 += __shfl_down_sync(0xFFFFFFFFu, a1, off);
    }
    const int wrp = t >> 5, ln = t & 31;
    if (ln == 0) { smd[wrp] = md2; s0[wrp] = a0; s1[wrp] = a1; }
    __syncthreads();

    if (t == 0) {
        md2 = fminf(fminf(smd[0], smd[1]), fminf(smd[2], smd[3]));
        a0  = s0[0] + s0[1] + s0[2] + s0[3];
        a1  = s1[0] + s1[1] + s1[2] + s1[3];

        const float md = sqrtf(md2);
        const float thr_lo = 22.62741699796952f;        // sqrt(2)*16
        const bool sel = valid && (md > thr_lo) && (md < 130.0f);

        const float l0 = a0 + bn[0];
        const float l1 = a1 + bn[1];
        const float d  = l1 - l0;
        // ce = logsumexp([l0,l1]) - l0, numerically stable
        const float ce = fmaxf(d, 0.0f) + log1pf(expf(-fabsf(d)));

        g_ce[i]  = sel ? ce : 0.0f;
        g_sel[i] = sel ? 1.0f : 0.0f;
        __threadfence();
        const int ticket = atomicAdd(&g_counter, 1);
        s_last = (ticket == NBC - 1);
    }
    __syncthreads();

    // ---- last block performs the deterministic final reduction ----
    if (s_last) {
        __threadfence();
        float ce = 0.0f, sl = 0.0f;
        for (int k = t; k < NBC; k += TPB) { ce += g_ce[k]; sl += g_sel[k]; }
        #pragma unroll
        for (int off = 16; off > 0; off >>= 1) {
            ce += __shfl_down_sync(0xFFFFFFFFu, ce, off);
            sl += __shfl_down_sync(0xFFFFFFFFu, sl, off);
        }
        if (ln == 0) { s0[wrp] = ce; s1[wrp] = sl; }
        __syncthreads();
        if (t == 0) {
            ce = s0[0] + s0[1] + s0[2] + s0[3];
            sl = s1[0] + s1[1] + s1[2] + s1[3];
            out[0] = ce / fmaxf(sl, 1.0f);
            g_counter = 0;   // reset for next graph replay
        }
    }
}

extern "C" void kernel_launch(void* const* d_in, const int* in_sizes, int n_in,
                              void* d_out, int out_size) {
    const float* lane_xs = (const float*)d_in[0];
    const float* lane_ys = (const float*)d_in[1];
    const float* centers = (const float*)d_in[2];
    const float* feat    = (const float*)d_in[3];
    const float* Wn      = (const float*)d_in[4];
    const float* bn      = (const float*)d_in[5];
    float* out = (float*)d_out;

    loss_point_kernel<<<NBC, TPB>>>(lane_xs, lane_ys, centers, feat, Wn, bn, out);
}